// round 6
// baseline (speedup 1.0000x reference)
#include <cuda_runtime.h>
#include <cstdint>

#define N_NODES 50000
#define N_EDGES 800000
#define F_IN    128
#define HIDDEN  256
#define N_GRAPHS 128
#define BUCKET  64   // max in-degree capacity; P(overflow) ~ 1e-17 for Binom(800k, 1/50k)

// ---------------- scratch (static device globals; no allocation) ----------------
__device__ float g_bufA[N_NODES * HIDDEN];
__device__ float g_bufB[N_NODES * HIDDEN];
__device__ int   g_fill[N_NODES];
__device__ int   g_csr_src[N_NODES * BUCKET];
__device__ float g_csr_w[N_NODES * BUCKET];
__device__ int   g_gstart[N_GRAPHS + 1];

// ---------------- bucket CSR build ----------------
__global__ void k_zero_fill() {
    int i = blockIdx.x * blockDim.x + threadIdx.x;
    if (i < N_NODES) g_fill[i] = 0;
}

__global__ void k_scatter(const int* __restrict__ edge_src,
                          const int* __restrict__ edge_dst,
                          const float* __restrict__ edge_w) {
    int e = blockIdx.x * blockDim.x + threadIdx.x;
    if (e >= N_EDGES) return;
    int d = edge_dst[e];
    int pos = atomicAdd(&g_fill[d], 1);
    if (pos < BUCKET) {
        int o = d * BUCKET + pos;
        g_csr_src[o] = edge_src[e];
        g_csr_w[o]   = edge_w[e];
    }
}

__global__ void k_gstart(const int* __restrict__ seg_ids) {
    int i = blockIdx.x * blockDim.x + threadIdx.x;
    if (i >= N_NODES) return;
    int s = seg_ids[i];
    int p = (i > 0) ? seg_ids[i - 1] : -1;
    for (int g = p + 1; g <= s; g++) g_gstart[g] = i;
    if (i == N_NODES - 1)
        for (int g = s + 1; g <= N_GRAPHS; g++) g_gstart[g] = N_NODES;
}

// ---------------- 3xTF32 tensor GEMM: C = relu(A[M,K] @ B[K,256] + bias) ----------------
// 128x128 block tile, BK=32, 256 threads (8 warps 2Mx4N), warp tile 64x32.
// SMEM holds raw fp32; hi/lo tf32 split computed at fragment load.
// acc += a_hi*b_hi + a_lo*b_hi + a_hi*b_lo  (error ~2^-22)
#define GBM 128
#define GBN 128
#define GBK 32
#define AS_STRIDE 36    // 32 + 4 pad
#define BS_STRIDE 132   // 128 + 4 pad

__device__ __forceinline__ uint32_t tf32_hi(float x) {
    uint32_t o;
    asm("cvt.rna.tf32.f32 %0, %1;" : "=r"(o) : "f"(x));
    return o;
}

__global__ __launch_bounds__(256) void k_gemm_tf32x3(const float* __restrict__ A,
                                                     int K,
                                                     const float* __restrict__ Bw,
                                                     const float* __restrict__ bias,
                                                     float* __restrict__ C,
                                                     int M) {
    __shared__ float As[GBM * AS_STRIDE];   // raw fp32 [row][k]
    __shared__ float Bs[GBK * BS_STRIDE];   // raw fp32 [k][n]

    int tid  = threadIdx.x;
    int lane = tid & 31;
    int warp = tid >> 5;
    int wm = warp & 1;        // M offset 0/64
    int wn = warp >> 1;       // N offset 0/32/64/96

    int rowBase = blockIdx.y * GBM;
    int colBase = blockIdx.x * GBN;

    float acc[4][4][4];
#pragma unroll
    for (int mi = 0; mi < 4; mi++)
#pragma unroll
        for (int ni = 0; ni < 4; ni++)
#pragma unroll
            for (int r = 0; r < 4; r++) acc[mi][ni][r] = 0.0f;

    for (int kt = 0; kt < K; kt += GBK) {
        // load A tile 128x32 (4 float4/thread)
#pragma unroll
        for (int i = 0; i < 4; i++) {
            int f = tid + 256 * i;
            int row = f >> 3;
            int kc  = (f & 7) * 4;
            int gr = rowBase + row;
            float4 v = make_float4(0.f, 0.f, 0.f, 0.f);
            if (gr < M) v = *(const float4*)&A[(long)gr * K + kt + kc];
            *(float4*)&As[row * AS_STRIDE + kc] = v;
        }
        // load B tile 32x128 (4 float4/thread)
#pragma unroll
        for (int i = 0; i < 4; i++) {
            int f = tid + 256 * i;
            int krow = f >> 5;
            int nc   = (f & 31) * 4;
            float4 v = *(const float4*)&Bw[(long)(kt + krow) * HIDDEN + colBase + nc];
            *(float4*)&Bs[krow * BS_STRIDE + nc] = v;
        }
        __syncthreads();

#pragma unroll
        for (int kk = 0; kk < GBK; kk += 8) {
            uint32_t ah[4][4], al[4][4], bh[4][2], bl[4][2];
#pragma unroll
            for (int mi = 0; mi < 4; mi++) {
                int r0 = wm * 64 + mi * 16 + (lane >> 2);
                int kc = kk + (lane & 3);
                float f0 = As[r0 * AS_STRIDE + kc];
                float f1 = As[(r0 + 8) * AS_STRIDE + kc];
                float f2 = As[r0 * AS_STRIDE + kc + 4];
                float f3 = As[(r0 + 8) * AS_STRIDE + kc + 4];
                ah[mi][0] = tf32_hi(f0); al[mi][0] = tf32_hi(f0 - __uint_as_float(ah[mi][0]));
                ah[mi][1] = tf32_hi(f1); al[mi][1] = tf32_hi(f1 - __uint_as_float(ah[mi][1]));
                ah[mi][2] = tf32_hi(f2); al[mi][2] = tf32_hi(f2 - __uint_as_float(ah[mi][2]));
                ah[mi][3] = tf32_hi(f3); al[mi][3] = tf32_hi(f3 - __uint_as_float(ah[mi][3]));
            }
#pragma unroll
            for (int ni = 0; ni < 4; ni++) {
                int cb = wn * 32 + ni * 8 + (lane >> 2);
                int kc = kk + (lane & 3);
                float f0 = Bs[kc * BS_STRIDE + cb];
                float f1 = Bs[(kc + 4) * BS_STRIDE + cb];
                bh[ni][0] = tf32_hi(f0); bl[ni][0] = tf32_hi(f0 - __uint_as_float(bh[ni][0]));
                bh[ni][1] = tf32_hi(f1); bl[ni][1] = tf32_hi(f1 - __uint_as_float(bh[ni][1]));
            }
#define MMA_T(AF, BF)                                                          \
            asm volatile(                                                      \
                "mma.sync.aligned.m16n8k8.row.col.f32.tf32.tf32.f32 "          \
                "{%0,%1,%2,%3}, {%4,%5,%6,%7}, {%8,%9}, {%0,%1,%2,%3};"        \
                : "+f"(acc[mi][ni][0]), "+f"(acc[mi][ni][1]),                  \
                  "+f"(acc[mi][ni][2]), "+f"(acc[mi][ni][3])                   \
                : "r"(AF[mi][0]), "r"(AF[mi][1]),                              \
                  "r"(AF[mi][2]), "r"(AF[mi][3]),                              \
                  "r"(BF[ni][0]), "r"(BF[ni][1]))
#pragma unroll
            for (int mi = 0; mi < 4; mi++)
#pragma unroll
                for (int ni = 0; ni < 4; ni++) { MMA_T(al, bh); }
#pragma unroll
            for (int mi = 0; mi < 4; mi++)
#pragma unroll
                for (int ni = 0; ni < 4; ni++) { MMA_T(ah, bl); }
#pragma unroll
            for (int mi = 0; mi < 4; mi++)
#pragma unroll
                for (int ni = 0; ni < 4; ni++) { MMA_T(ah, bh); }
#undef MMA_T
        }
        __syncthreads();
    }

    // epilogue: bias + relu + store
#pragma unroll
    for (int mi = 0; mi < 4; mi++) {
        int r0 = rowBase + wm * 64 + mi * 16 + (lane >> 2);
#pragma unroll
        for (int ni = 0; ni < 4; ni++) {
            int col = colBase + wn * 32 + ni * 8 + (lane & 3) * 2;
            float b0 = bias[col], b1v = bias[col + 1];
            if (r0 < M) {
                float2 o;
                o.x = fmaxf(acc[mi][ni][0] + b0, 0.f);
                o.y = fmaxf(acc[mi][ni][1] + b1v, 0.f);
                *(float2*)&C[(long)r0 * HIDDEN + col] = o;
            }
            if (r0 + 8 < M) {
                float2 o;
                o.x = fmaxf(acc[mi][ni][2] + b0, 0.f);
                o.y = fmaxf(acc[mi][ni][3] + b1v, 0.f);
                *(float2*)&C[(long)(r0 + 8) * HIDDEN + col] = o;
            }
        }
    }
}

// ---------------- SpMM (gather-sum over bucket CSR) ----------------
// 128-col: 1 warp/node, float4/lane.
__global__ __launch_bounds__(256) void k_spmm128(const float* __restrict__ in,
                                                 float* __restrict__ out) {
    int node = blockIdx.x * 8 + (threadIdx.x >> 5);
    if (node >= N_NODES) return;
    int c = (threadIdx.x & 31) * 4;
    int beg = node * BUCKET;
    int end = beg + g_fill[node];

    float4 acc = make_float4(0.f, 0.f, 0.f, 0.f);
    int e = beg;
    for (; e + 4 <= end; e += 4) {
        int s0 = g_csr_src[e], s1 = g_csr_src[e + 1];
        int s2 = g_csr_src[e + 2], s3 = g_csr_src[e + 3];
        float w0 = g_csr_w[e], w1 = g_csr_w[e + 1];
        float w2 = g_csr_w[e + 2], w3 = g_csr_w[e + 3];
        float4 v0 = *(const float4*)&in[(long)s0 * F_IN + c];
        float4 v1 = *(const float4*)&in[(long)s1 * F_IN + c];
        float4 v2 = *(const float4*)&in[(long)s2 * F_IN + c];
        float4 v3 = *(const float4*)&in[(long)s3 * F_IN + c];
        acc.x = fmaf(v0.x, w0, acc.x); acc.y = fmaf(v0.y, w0, acc.y);
        acc.z = fmaf(v0.z, w0, acc.z); acc.w = fmaf(v0.w, w0, acc.w);
        acc.x = fmaf(v1.x, w1, acc.x); acc.y = fmaf(v1.y, w1, acc.y);
        acc.z = fmaf(v1.z, w1, acc.z); acc.w = fmaf(v1.w, w1, acc.w);
        acc.x = fmaf(v2.x, w2, acc.x); acc.y = fmaf(v2.y, w2, acc.y);
        acc.z = fmaf(v2.z, w2, acc.z); acc.w = fmaf(v2.w, w2, acc.w);
        acc.x = fmaf(v3.x, w3, acc.x); acc.y = fmaf(v3.y, w3, acc.y);
        acc.z = fmaf(v3.z, w3, acc.z); acc.w = fmaf(v3.w, w3, acc.w);
    }
    for (; e < end; e++) {
        int s = g_csr_src[e];
        float w = g_csr_w[e];
        float4 v = *(const float4*)&in[(long)s * F_IN + c];
        acc.x = fmaf(v.x, w, acc.x); acc.y = fmaf(v.y, w, acc.y);
        acc.z = fmaf(v.z, w, acc.z); acc.w = fmaf(v.w, w, acc.w);
    }
    *(float4*)&out[(long)node * F_IN + c] = acc;
}

// 256-col: 64 threads/node.
__global__ __launch_bounds__(256) void k_spmm256(const float* __restrict__ in,
                                                 float* __restrict__ out) {
    int node = blockIdx.x * 4 + (threadIdx.x >> 6);
    if (node >= N_NODES) return;
    int c = (threadIdx.x & 63) * 4;
    int beg = node * BUCKET;
    int end = beg + g_fill[node];

    float4 acc = make_float4(0.f, 0.f, 0.f, 0.f);
    int e = beg;
    for (; e + 4 <= end; e += 4) {
        int s0 = g_csr_src[e], s1 = g_csr_src[e + 1];
        int s2 = g_csr_src[e + 2], s3 = g_csr_src[e + 3];
        float w0 = g_csr_w[e], w1 = g_csr_w[e + 1];
        float w2 = g_csr_w[e + 2], w3 = g_csr_w[e + 3];
        float4 v0 = *(const float4*)&in[(long)s0 * HIDDEN + c];
        float4 v1 = *(const float4*)&in[(long)s1 * HIDDEN + c];
        float4 v2 = *(const float4*)&in[(long)s2 * HIDDEN + c];
        float4 v3 = *(const float4*)&in[(long)s3 * HIDDEN + c];
        acc.x = fmaf(v0.x, w0, acc.x); acc.y = fmaf(v0.y, w0, acc.y);
        acc.z = fmaf(v0.z, w0, acc.z); acc.w = fmaf(v0.w, w0, acc.w);
        acc.x = fmaf(v1.x, w1, acc.x); acc.y = fmaf(v1.y, w1, acc.y);
        acc.z = fmaf(v1.z, w1, acc.z); acc.w = fmaf(v1.w, w1, acc.w);
        acc.x = fmaf(v2.x, w2, acc.x); acc.y = fmaf(v2.y, w2, acc.y);
        acc.z = fmaf(v2.z, w2, acc.z); acc.w = fmaf(v2.w, w2, acc.w);
        acc.x = fmaf(v3.x, w3, acc.x); acc.y = fmaf(v3.y, w3, acc.y);
        acc.z = fmaf(v3.z, w3, acc.z); acc.w = fmaf(v3.w, w3, acc.w);
    }
    for (; e < end; e++) {
        int s = g_csr_src[e];
        float w = g_csr_w[e];
        float4 v = *(const float4*)&in[(long)s * HIDDEN + c];
        acc.x = fmaf(v.x, w, acc.x); acc.y = fmaf(v.y, w, acc.y);
        acc.z = fmaf(v.z, w, acc.z); acc.w = fmaf(v.w, w, acc.w);
    }
    *(float4*)&out[(long)node * HIDDEN + c] = acc;
}

// ---------------- fused pool + head: out[g] = relu(pool_g @ Wd + bd) @ Wo + bo ----------------
__global__ __launch_bounds__(256) void k_poolhead(const float* __restrict__ h,
                                                  const float* __restrict__ Wd,
                                                  const float* __restrict__ bd,
                                                  const float* __restrict__ Wo,
                                                  const float* __restrict__ bo,
                                                  float* __restrict__ out) {
    __shared__ float pg[HIDDEN];
    __shared__ float red[256];
    int g = blockIdx.x;
    int j = threadIdx.x;
    int beg = g_gstart[g], end = g_gstart[g + 1];

    float acc0 = 0.f, acc1 = 0.f, acc2 = 0.f, acc3 = 0.f;
    int n = beg;
    for (; n + 4 <= end; n += 4) {
        acc0 += h[(long)n * HIDDEN + j];
        acc1 += h[(long)(n + 1) * HIDDEN + j];
        acc2 += h[(long)(n + 2) * HIDDEN + j];
        acc3 += h[(long)(n + 3) * HIDDEN + j];
    }
    for (; n < end; n++) acc0 += h[(long)n * HIDDEN + j];
    pg[j] = (acc0 + acc1) + (acc2 + acc3);
    __syncthreads();

    float acc = 0.f;
#pragma unroll 8
    for (int k = 0; k < HIDDEN; k++)
        acc = fmaf(pg[k], Wd[k * HIDDEN + j], acc);
    float v = fmaxf(acc + bd[j], 0.f);
    red[j] = v * Wo[j];
    __syncthreads();
    for (int s = 128; s > 0; s >>= 1) {
        if (j < s) red[j] += red[j + s];
        __syncthreads();
    }
    if (j == 0) out[g] = red[0] + bo[0];
}

// ---------------- launch ----------------
extern "C" void kernel_launch(void* const* d_in, const int* in_sizes, int n_in,
                              void* d_out, int out_size) {
    const float* x        = (const float*)d_in[0];
    const int*   edge_src = (const int*)d_in[1];
    const int*   edge_dst = (const int*)d_in[2];
    const float* edge_w   = (const float*)d_in[3];
    const int*   seg_ids  = (const int*)d_in[4];
    const float* W1       = (const float*)d_in[5];
    const float* b1       = (const float*)d_in[6];
    const float* W2       = (const float*)d_in[7];
    const float* b2       = (const float*)d_in[8];
    const float* Wd       = (const float*)d_in[9];
    const float* bd       = (const float*)d_in[10];
    const float* Wo       = (const float*)d_in[11];
    const float* bo       = (const float*)d_in[12];
    float* out = (float*)d_out;

    float* bufA; cudaGetSymbolAddress((void**)&bufA, g_bufA);
    float* bufB; cudaGetSymbolAddress((void**)&bufB, g_bufB);

    // bucket CSR build (no histogram, no scan)
    k_zero_fill<<<(N_NODES + 255) / 256, 256>>>();
    k_scatter<<<(N_EDGES + 255) / 256, 256>>>(edge_src, edge_dst, edge_w);
    k_gstart<<<(N_NODES + 255) / 256, 256>>>(seg_ids);

    dim3 gemmGrid(HIDDEN / GBN, (N_NODES + GBM - 1) / GBM);

    // layer 1 (reordered): s1 = A@x (128 cols); h1 = relu(s1 @ W1 + b1)
    k_spmm128<<<(N_NODES + 7) / 8, 256>>>(x, bufA);
    k_gemm_tf32x3<<<gemmGrid, 256>>>(bufA, F_IN, W1, b1, bufB, N_NODES);

    // layer 2 (reordered): s2 = A@h1 (256 cols); h2 = relu(s2 @ W2 + b2)
    k_spmm256<<<(N_NODES + 3) / 4, 256>>>(bufB, bufA);
    k_gemm_tf32x3<<<gemmGrid, 256>>>(bufA, HIDDEN, W2, b2, bufB, N_NODES);

    // fused pool + head
    k_poolhead<<<N_GRAPHS, HIDDEN>>>(bufB, Wd, bd, Wo, bo, out);
}

// round 12
// speedup vs baseline: 1.3258x; 1.3258x over previous
#include <cuda_runtime.h>
#include <cuda_bf16.h>
#include <cstdint>

#define N_NODES 50000
#define N_EDGES 800000
#define F_IN    128
#define HIDDEN  256
#define N_GRAPHS 128
#define BUCKET  64   // max in-degree capacity; P(overflow) ~ 1e-17 for Binom(800k, 1/50k)

// ---------------- scratch (static device globals; no allocation) ----------------
__device__ float g_bufA[N_NODES * HIDDEN];
__device__ float g_bufB[N_NODES * HIDDEN];
__device__ int   g_fill[N_NODES];
__device__ int2  g_csr[N_NODES * BUCKET];     // (src, w-bits)
__device__ int   g_gstart[N_GRAPHS + 1];
// weights transposed to [N][K] K-major, bf16 hi/lo split (16B-aligned for uint4 loads)
__device__ __align__(16) __nv_bfloat16 g_W1hi[HIDDEN * F_IN];
__device__ __align__(16) __nv_bfloat16 g_W1lo[HIDDEN * F_IN];
__device__ __align__(16) __nv_bfloat16 g_W2hi[HIDDEN * HIDDEN];
__device__ __align__(16) __nv_bfloat16 g_W2lo[HIDDEN * HIDDEN];

// ---------------- fused setup: zero fill + gstart + weight prep ----------------
__global__ void k_setup(const int* __restrict__ seg_ids,
                        const float* __restrict__ W1,
                        const float* __restrict__ W2) {
    int i = blockIdx.x * blockDim.x + threadIdx.x;
    if (i < N_NODES) {
        g_fill[i] = 0;
        int s = seg_ids[i];
        int p = (i > 0) ? seg_ids[i - 1] : -1;
        for (int g = p + 1; g <= s; g++) g_gstart[g] = i;
        if (i == N_NODES - 1)
            for (int g = s + 1; g <= N_GRAPHS; g++) g_gstart[g] = N_NODES;
    }
    if (i < HIDDEN * F_IN) {
        int n = i / F_IN, k = i % F_IN;
        float v = W1[k * HIDDEN + n];
        __nv_bfloat16 h = __float2bfloat16_rn(v);
        g_W1hi[n * F_IN + k] = h;
        g_W1lo[n * F_IN + k] = __float2bfloat16_rn(v - __bfloat162float(h));
    }
    if (i < HIDDEN * HIDDEN) {
        int n = i / HIDDEN, k = i % HIDDEN;
        float v = W2[k * HIDDEN + n];
        __nv_bfloat16 h = __float2bfloat16_rn(v);
        g_W2hi[n * HIDDEN + k] = h;
        g_W2lo[n * HIDDEN + k] = __float2bfloat16_rn(v - __bfloat162float(h));
    }
}

__global__ void k_scatter(const int* __restrict__ edge_src,
                          const int* __restrict__ edge_dst,
                          const float* __restrict__ edge_w) {
    int e = blockIdx.x * blockDim.x + threadIdx.x;
    if (e >= N_EDGES) return;
    int d = edge_dst[e];
    int pos = atomicAdd(&g_fill[d], 1);
    if (pos < BUCKET)
        g_csr[d * BUCKET + pos] = make_int2(edge_src[e], __float_as_int(edge_w[e]));
}

// ---------------- bf16x3 tensor GEMM: C = relu(A[M,K] @ W[K,256] + bias) ----------------
// 128x128 block tile, BK=32, 256 threads (8 warps 2Mx4N), warp tile 64x32.
// mma.sync.m16n8k16 bf16, fp32 accumulate. hi/lo split done at SMEM store.
// acc = ah*bh + al*bh + ah*bl  (error ~2^-17)
#define GBM 128
#define GBN 128
#define GBK 32
#define TS 40   // SMEM row stride in bf16 elems (32 + 8 pad) -> 80B rows

__global__ __launch_bounds__(256) void k_gemm_bf16x3(const float* __restrict__ A, int K,
                                                     const __nv_bfloat16* __restrict__ Whi,
                                                     const __nv_bfloat16* __restrict__ Wlo,
                                                     const float* __restrict__ bias,
                                                     float* __restrict__ C, int M) {
    __shared__ __align__(16) __nv_bfloat16 Ahi[GBM * TS];
    __shared__ __align__(16) __nv_bfloat16 Alo[GBM * TS];
    __shared__ __align__(16) __nv_bfloat16 Bhi[GBN * TS];   // [n][k] K-major
    __shared__ __align__(16) __nv_bfloat16 Blo[GBN * TS];

    int tid  = threadIdx.x;
    int lane = tid & 31;
    int warp = tid >> 5;
    int wm = warp & 1;        // M offset 0/64
    int wn = warp >> 1;       // N offset 0/32/64/96

    int rowBase = blockIdx.y * GBM;
    int colBase = blockIdx.x * GBN;

    float acc[4][4][4];
#pragma unroll
    for (int mi = 0; mi < 4; mi++)
#pragma unroll
        for (int ni = 0; ni < 4; ni++)
#pragma unroll
            for (int r = 0; r < 4; r++) acc[mi][ni][r] = 0.0f;

    int ldrow = tid >> 1;            // 0..127
    int ldk   = (tid & 1) * 16;      // 0 or 16  (each thread owns 16 k-values)

    for (int kt = 0; kt < K; kt += GBK) {
        // ---- A tile 128x32 fp32 -> bf16 hi/lo (16 values per thread) ----
        {
            bool valid = (rowBase + ldrow) < M;
            const float* src = A + (long)(rowBase + ldrow) * K + kt + ldk;
#pragma unroll
            for (int i = 0; i < 4; i++) {
                float4 v = valid ? *(const float4*)(src + i * 4)
                                 : make_float4(0.f, 0.f, 0.f, 0.f);
                __nv_bfloat16 hx = __float2bfloat16_rn(v.x);
                __nv_bfloat16 hy = __float2bfloat16_rn(v.y);
                __nv_bfloat16 hz = __float2bfloat16_rn(v.z);
                __nv_bfloat16 hw = __float2bfloat16_rn(v.w);
                __nv_bfloat162 h01; h01.x = hx; h01.y = hy;
                __nv_bfloat162 h23; h23.x = hz; h23.y = hw;
                __nv_bfloat162 l01, l23;
                l01.x = __float2bfloat16_rn(v.x - __bfloat162float(hx));
                l01.y = __float2bfloat16_rn(v.y - __bfloat162float(hy));
                l23.x = __float2bfloat16_rn(v.z - __bfloat162float(hz));
                l23.y = __float2bfloat16_rn(v.w - __bfloat162float(hw));
                int o = ldrow * TS + ldk + i * 4;
                *(__nv_bfloat162*)&Ahi[o]     = h01;
                *(__nv_bfloat162*)&Ahi[o + 2] = h23;
                *(__nv_bfloat162*)&Alo[o]     = l01;
                *(__nv_bfloat162*)&Alo[o + 2] = l23;
            }
        }
        // ---- B tile [128 n][32 k] bf16, pre-split in global ----
        // FIX (R9 NaN): each thread owns 16 bf16 = TWO uint4 loads, not one.
        {
            const __nv_bfloat16* sh = Whi + (long)(colBase + ldrow) * K + kt + ldk;
            const __nv_bfloat16* sl = Wlo + (long)(colBase + ldrow) * K + kt + ldk;
            int o = ldrow * TS + ldk;
            *(uint4*)&Bhi[o]     = *(const uint4*)sh;
            *(uint4*)&Bhi[o + 8] = *(const uint4*)(sh + 8);
            *(uint4*)&Blo[o]     = *(const uint4*)sl;
            *(uint4*)&Blo[o + 8] = *(const uint4*)(sl + 8);
        }
        __syncthreads();

#pragma unroll
        for (int kk = 0; kk < GBK; kk += 16) {
            uint32_t ah[4][4], al[4][4], bh[4][2], bl[4][2];
            int cp = (lane & 3) * 2;           // k pair offset
            int rr = lane >> 2;                // 0..7
#pragma unroll
            for (int mi = 0; mi < 4; mi++) {
                int r0 = (wm * 64 + mi * 16 + rr) * TS + kk + cp;
                int r1 = r0 + 8 * TS;
                ah[mi][0] = *(const uint32_t*)&Ahi[r0];
                ah[mi][1] = *(const uint32_t*)&Ahi[r1];
                ah[mi][2] = *(const uint32_t*)&Ahi[r0 + 8];
                ah[mi][3] = *(const uint32_t*)&Ahi[r1 + 8];
                al[mi][0] = *(const uint32_t*)&Alo[r0];
                al[mi][1] = *(const uint32_t*)&Alo[r1];
                al[mi][2] = *(const uint32_t*)&Alo[r0 + 8];
                al[mi][3] = *(const uint32_t*)&Alo[r1 + 8];
            }
#pragma unroll
            for (int ni = 0; ni < 4; ni++) {
                int nb = (wn * 32 + ni * 8 + rr) * TS + kk + cp;
                bh[ni][0] = *(const uint32_t*)&Bhi[nb];
                bh[ni][1] = *(const uint32_t*)&Bhi[nb + 8];
                bl[ni][0] = *(const uint32_t*)&Blo[nb];
                bl[ni][1] = *(const uint32_t*)&Blo[nb + 8];
            }
#define MMA_B(AF, BF)                                                          \
            asm volatile(                                                      \
                "mma.sync.aligned.m16n8k16.row.col.f32.bf16.bf16.f32 "         \
                "{%0,%1,%2,%3}, {%4,%5,%6,%7}, {%8,%9}, {%0,%1,%2,%3};"        \
                : "+f"(acc[mi][ni][0]), "+f"(acc[mi][ni][1]),                  \
                  "+f"(acc[mi][ni][2]), "+f"(acc[mi][ni][3])                   \
                : "r"(AF[mi][0]), "r"(AF[mi][1]),                              \
                  "r"(AF[mi][2]), "r"(AF[mi][3]),                              \
                  "r"(BF[ni][0]), "r"(BF[ni][1]))
#pragma unroll
            for (int mi = 0; mi < 4; mi++)
#pragma unroll
                for (int ni = 0; ni < 4; ni++) { MMA_B(al, bh); }
#pragma unroll
            for (int mi = 0; mi < 4; mi++)
#pragma unroll
                for (int ni = 0; ni < 4; ni++) { MMA_B(ah, bl); }
#pragma unroll
            for (int mi = 0; mi < 4; mi++)
#pragma unroll
                for (int ni = 0; ni < 4; ni++) { MMA_B(ah, bh); }
#undef MMA_B
        }
        __syncthreads();
    }

    // epilogue: bias + relu + store (m16n8 accum layout)
#pragma unroll
    for (int mi = 0; mi < 4; mi++) {
        int r0 = rowBase + wm * 64 + mi * 16 + (lane >> 2);
#pragma unroll
        for (int ni = 0; ni < 4; ni++) {
            int col = colBase + wn * 32 + ni * 8 + (lane & 3) * 2;
            float b0 = bias[col], b1v = bias[col + 1];
            if (r0 < M) {
                float2 o;
                o.x = fmaxf(acc[mi][ni][0] + b0, 0.f);
                o.y = fmaxf(acc[mi][ni][1] + b1v, 0.f);
                *(float2*)&C[(long)r0 * HIDDEN + col] = o;
            }
            if (r0 + 8 < M) {
                float2 o;
                o.x = fmaxf(acc[mi][ni][2] + b0, 0.f);
                o.y = fmaxf(acc[mi][ni][3] + b1v, 0.f);
                *(float2*)&C[(long)(r0 + 8) * HIDDEN + col] = o;
            }
        }
    }
}

// ---------------- SpMM (gather-sum over bucket CSR, packed int2 edges) ----------------
// 128-col: 1 warp per node, float4 per lane.
__global__ __launch_bounds__(256) void k_spmm128(const float* __restrict__ in,
                                                 float* __restrict__ out) {
    int node = blockIdx.x * 8 + (threadIdx.x >> 5);
    if (node >= N_NODES) return;
    int c = (threadIdx.x & 31) * 4;
    int beg = node * BUCKET;
    int end = beg + g_fill[node];

    float4 acc = make_float4(0.f, 0.f, 0.f, 0.f);
    int e = beg;
    for (; e + 4 <= end; e += 4) {
        int4 p = *(const int4*)&g_csr[e];       // (s0,w0,s1,w1)
        int4 q = *(const int4*)&g_csr[e + 2];   // (s2,w2,s3,w3)
        float w0 = __int_as_float(p.y), w1 = __int_as_float(p.w);
        float w2 = __int_as_float(q.y), w3 = __int_as_float(q.w);
        float4 v0 = *(const float4*)&in[(long)p.x * F_IN + c];
        float4 v1 = *(const float4*)&in[(long)p.z * F_IN + c];
        float4 v2 = *(const float4*)&in[(long)q.x * F_IN + c];
        float4 v3 = *(const float4*)&in[(long)q.z * F_IN + c];
        acc.x = fmaf(v0.x, w0, acc.x); acc.y = fmaf(v0.y, w0, acc.y);
        acc.z = fmaf(v0.z, w0, acc.z); acc.w = fmaf(v0.w, w0, acc.w);
        acc.x = fmaf(v1.x, w1, acc.x); acc.y = fmaf(v1.y, w1, acc.y);
        acc.z = fmaf(v1.z, w1, acc.z); acc.w = fmaf(v1.w, w1, acc.w);
        acc.x = fmaf(v2.x, w2, acc.x); acc.y = fmaf(v2.y, w2, acc.y);
        acc.z = fmaf(v2.z, w2, acc.z); acc.w = fmaf(v2.w, w2, acc.w);
        acc.x = fmaf(v3.x, w3, acc.x); acc.y = fmaf(v3.y, w3, acc.y);
        acc.z = fmaf(v3.z, w3, acc.z); acc.w = fmaf(v3.w, w3, acc.w);
    }
    for (; e < end; e++) {
        int2 p = g_csr[e];
        float w = __int_as_float(p.y);
        float4 v = *(const float4*)&in[(long)p.x * F_IN + c];
        acc.x = fmaf(v.x, w, acc.x); acc.y = fmaf(v.y, w, acc.y);
        acc.z = fmaf(v.z, w, acc.z); acc.w = fmaf(v.w, w, acc.w);
    }
    *(float4*)&out[(long)node * F_IN + c] = acc;
}

// 256-col: 64 threads per node.
__global__ __launch_bounds__(256) void k_spmm256(const float* __restrict__ in,
                                                 float* __restrict__ out) {
    int node = blockIdx.x * 4 + (threadIdx.x >> 6);
    if (node >= N_NODES) return;
    int c = (threadIdx.x & 63) * 4;
    int beg = node * BUCKET;
    int end = beg + g_fill[node];

    float4 acc = make_float4(0.f, 0.f, 0.f, 0.f);
    int e = beg;
    for (; e + 4 <= end; e += 4) {
        int4 p = *(const int4*)&g_csr[e];
        int4 q = *(const int4*)&g_csr[e + 2];
        float w0 = __int_as_float(p.y), w1 = __int_as_float(p.w);
        float w2 = __int_as_float(q.y), w3 = __int_as_float(q.w);
        float4 v0 = *(const float4*)&in[(long)p.x * HIDDEN + c];
        float4 v1 = *(const float4*)&in[(long)p.z * HIDDEN + c];
        float4 v2 = *(const float4*)&in[(long)q.x * HIDDEN + c];
        float4 v3 = *(const float4*)&in[(long)q.z * HIDDEN + c];
        acc.x = fmaf(v0.x, w0, acc.x); acc.y = fmaf(v0.y, w0, acc.y);
        acc.z = fmaf(v0.z, w0, acc.z); acc.w = fmaf(v0.w, w0, acc.w);
        acc.x = fmaf(v1.x, w1, acc.x); acc.y = fmaf(v1.y, w1, acc.y);
        acc.z = fmaf(v1.z, w1, acc.z); acc.w = fmaf(v1.w, w1, acc.w);
        acc.x = fmaf(v2.x, w2, acc.x); acc.y = fmaf(v2.y, w2, acc.y);
        acc.z = fmaf(v2.z, w2, acc.z); acc.w = fmaf(v2.w, w2, acc.w);
        acc.x = fmaf(v3.x, w3, acc.x); acc.y = fmaf(v3.y, w3, acc.y);
        acc.z = fmaf(v3.z, w3, acc.z); acc.w = fmaf(v3.w, w3, acc.w);
    }
    for (; e < end; e++) {
        int2 p = g_csr[e];
        float w = __int_as_float(p.y);
        float4 v = *(const float4*)&in[(long)p.x * HIDDEN + c];
        acc.x = fmaf(v.x, w, acc.x); acc.y = fmaf(v.y, w, acc.y);
        acc.z = fmaf(v.z, w, acc.z); acc.w = fmaf(v.w, w, acc.w);
    }
    *(float4*)&out[(long)node * HIDDEN + c] = acc;
}

// ---------------- fused pool + head ----------------
__global__ __launch_bounds__(256) void k_poolhead(const float* __restrict__ h,
                                                  const float* __restrict__ Wd,
                                                  const float* __restrict__ bd,
                                                  const float* __restrict__ Wo,
                                                  const float* __restrict__ bo,
                                                  float* __restrict__ out) {
    __shared__ float pg[HIDDEN];
    __shared__ float red[256];
    int g = blockIdx.x;
    int j = threadIdx.x;
    int beg = g_gstart[g], end = g_gstart[g + 1];

    float acc0 = 0.f, acc1 = 0.f, acc2 = 0.f, acc3 = 0.f;
    int n = beg;
    for (; n + 4 <= end; n += 4) {
        acc0 += h[(long)n * HIDDEN + j];
        acc1 += h[(long)(n + 1) * HIDDEN + j];
        acc2 += h[(long)(n + 2) * HIDDEN + j];
        acc3 += h[(long)(n + 3) * HIDDEN + j];
    }
    for (; n < end; n++) acc0 += h[(long)n * HIDDEN + j];
    pg[j] = (acc0 + acc1) + (acc2 + acc3);
    __syncthreads();

    float acc = 0.f;
#pragma unroll 8
    for (int k = 0; k < HIDDEN; k++)
        acc = fmaf(pg[k], Wd[k * HIDDEN + j], acc);
    float v = fmaxf(acc + bd[j], 0.f);
    red[j] = v * Wo[j];
    __syncthreads();
    for (int s = 128; s > 0; s >>= 1) {
        if (j < s) red[j] += red[j + s];
        __syncthreads();
    }
    if (j == 0) out[g] = red[0] + bo[0];
}

// ---------------- launch ----------------
extern "C" void kernel_launch(void* const* d_in, const int* in_sizes, int n_in,
                              void* d_out, int out_size) {
    const float* x        = (const float*)d_in[0];
    const int*   edge_src = (const int*)d_in[1];
    const int*   edge_dst = (const int*)d_in[2];
    const float* edge_w   = (const float*)d_in[3];
    const int*   seg_ids  = (const int*)d_in[4];
    const float* W1       = (const float*)d_in[5];
    const float* b1       = (const float*)d_in[6];
    const float* W2       = (const float*)d_in[7];
    const float* b2       = (const float*)d_in[8];
    const float* Wd       = (const float*)d_in[9];
    const float* bd       = (const float*)d_in[10];
    const float* Wo       = (const float*)d_in[11];
    const float* bo       = (const float*)d_in[12];
    float* out = (float*)d_out;

    float* bufA; cudaGetSymbolAddress((void**)&bufA, g_bufA);
    float* bufB; cudaGetSymbolAddress((void**)&bufB, g_bufB);
    __nv_bfloat16* w1hi; cudaGetSymbolAddress((void**)&w1hi, g_W1hi);
    __nv_bfloat16* w1lo; cudaGetSymbolAddress((void**)&w1lo, g_W1lo);
    __nv_bfloat16* w2hi; cudaGetSymbolAddress((void**)&w2hi, g_W2hi);
    __nv_bfloat16* w2lo; cudaGetSymbolAddress((void**)&w2lo, g_W2lo);

    // setup (zero fill + gstart + weight split/transpose), then scatter
    k_setup<<<(HIDDEN * HIDDEN + 255) / 256, 256>>>(seg_ids, W1, W2);
    k_scatter<<<(N_EDGES + 255) / 256, 256>>>(edge_src, edge_dst, edge_w);

    dim3 gemmGrid(HIDDEN / GBN, (N_NODES + GBM - 1) / GBM);

    // layer 1 (reordered): s1 = A@x (128 cols); h1 = relu(s1 @ W1 + b1)
    k_spmm128<<<(N_NODES + 7) / 8, 256>>>(x, bufA);
    k_gemm_bf16x3<<<gemmGrid, 256>>>(bufA, F_IN, w1hi, w1lo, b1, bufB, N_NODES);

    // layer 2 (reordered): s2 = A@h1 (256 cols); h2 = relu(s2 @ W2 + b2)
    k_spmm256<<<(N_NODES + 3) / 4, 256>>>(bufB, bufA);
    k_gemm_bf16x3<<<gemmGrid, 256>>>(bufA, HIDDEN, w2hi, w2lo, b2, bufB, N_NODES);

    // fused pool + head
    k_poolhead<<<N_GRAPHS, HIDDEN>>>(bufB, Wd, bd, Wo, bo, out);
}

// round 13
// speedup vs baseline: 1.3431x; 1.0130x over previous
#include <cuda_runtime.h>
#include <cuda_bf16.h>
#include <cstdint>

#define N_NODES 50000
#define N_EDGES 800000
#define F_IN    128
#define HIDDEN  256
#define N_GRAPHS 128
#define BUCKET  64   // max in-degree; P(overflow) ~ 1e-17 for Binom(800k, 1/50k)

// ---------------- scratch (static device globals; no allocation) ----------------
__device__ float g_bufA[N_NODES * HIDDEN];   // h1 (fp32)
__device__ float g_bufB[N_NODES * HIDDEN];   // h2 (fp32)
__device__ __align__(16) __nv_bfloat16 g_sHi[N_NODES * HIDDEN];  // spmm out hi
__device__ __align__(16) __nv_bfloat16 g_sLo[N_NODES * HIDDEN];  // spmm out lo
__device__ int   g_fill[N_NODES];
__device__ int2  g_csr[N_NODES * BUCKET];    // (src, w-bits)
__device__ int   g_gstart[N_GRAPHS + 1];
// weights transposed to [N][K] K-major, bf16 hi/lo split
__device__ __align__(16) __nv_bfloat16 g_W1hi[HIDDEN * F_IN];
__device__ __align__(16) __nv_bfloat16 g_W1lo[HIDDEN * F_IN];
__device__ __align__(16) __nv_bfloat16 g_W2hi[HIDDEN * HIDDEN];
__device__ __align__(16) __nv_bfloat16 g_W2lo[HIDDEN * HIDDEN];

// ---------------- fused setup ----------------
__global__ void k_setup(const int* __restrict__ seg_ids,
                        const float* __restrict__ W1,
                        const float* __restrict__ W2) {
    int i = blockIdx.x * blockDim.x + threadIdx.x;
    if (i < N_NODES) {
        g_fill[i] = 0;
        int s = seg_ids[i];
        int p = (i > 0) ? seg_ids[i - 1] : -1;
        for (int g = p + 1; g <= s; g++) g_gstart[g] = i;
        if (i == N_NODES - 1)
            for (int g = s + 1; g <= N_GRAPHS; g++) g_gstart[g] = N_NODES;
    }
    if (i < HIDDEN * F_IN) {
        int n = i / F_IN, k = i % F_IN;
        float v = W1[k * HIDDEN + n];
        __nv_bfloat16 h = __float2bfloat16_rn(v);
        g_W1hi[n * F_IN + k] = h;
        g_W1lo[n * F_IN + k] = __float2bfloat16_rn(v - __bfloat162float(h));
    }
    if (i < HIDDEN * HIDDEN) {
        int n = i / HIDDEN, k = i % HIDDEN;
        float v = W2[k * HIDDEN + n];
        __nv_bfloat16 h = __float2bfloat16_rn(v);
        g_W2hi[n * HIDDEN + k] = h;
        g_W2lo[n * HIDDEN + k] = __float2bfloat16_rn(v - __bfloat162float(h));
    }
}

__global__ void k_scatter(const int* __restrict__ edge_src,
                          const int* __restrict__ edge_dst,
                          const float* __restrict__ edge_w) {
    int e = blockIdx.x * blockDim.x + threadIdx.x;
    if (e >= N_EDGES) return;
    int d = edge_dst[e];
    int pos = atomicAdd(&g_fill[d], 1);
    if (pos < BUCKET)
        g_csr[d * BUCKET + pos] = make_int2(edge_src[e], __float_as_int(edge_w[e]));
}

// ---------------- ptx helpers ----------------
__device__ __forceinline__ void cp16(uint32_t dst, const void* src, bool v) {
    asm volatile("cp.async.ca.shared.global [%0], [%1], 16, %2;"
                 :: "r"(dst), "l"(src), "r"(v ? 16 : 0) : "memory");
}
__device__ __forceinline__ void ldsm4(uint32_t* r, uint32_t a) {
    asm volatile("ldmatrix.sync.aligned.m8n8.x4.shared.b16 {%0,%1,%2,%3}, [%4];"
                 : "=r"(r[0]), "=r"(r[1]), "=r"(r[2]), "=r"(r[3]) : "r"(a));
}
__device__ __forceinline__ void ldsm2(uint32_t* r, uint32_t a) {
    asm volatile("ldmatrix.sync.aligned.m8n8.x2.shared.b16 {%0,%1}, [%2];"
                 : "=r"(r[0]), "=r"(r[1]) : "r"(a));
}

// ---------------- bf16x3 pipelined tensor GEMM ----------------
// C = relu(A(hi,lo)[M,K] @ W(hi,lo)[K,256] + bias)
// 128x128 tile, BK=32, 256 threads (8 warps 2Mx4N), warp tile 64x32.
// 2-stage cp.async pipeline; ldmatrix fragment loads; m16n8k16 bf16 MMA.
#define GBM 128
#define GBN 128
#define GBK 32
#define TS 40                         // bf16 row stride (32 + 8 pad) = 80B
#define ARR_ELEMS (128 * TS)          // 5120 bf16 = 10240 B
#define STAGE_BYTES (4 * ARR_ELEMS * 2)  // 40960 B
#define OFF_AHI 0
#define OFF_ALO (ARR_ELEMS * 2)
#define OFF_BHI (2 * ARR_ELEMS * 2)
#define OFF_BLO (3 * ARR_ELEMS * 2)
#define GEMM_SMEM (2 * STAGE_BYTES)   // 81920 B

__global__ __launch_bounds__(256) void k_gemm_pipe(
        const __nv_bfloat16* __restrict__ Ahi,
        const __nv_bfloat16* __restrict__ Alo, int K,
        const __nv_bfloat16* __restrict__ Whi,
        const __nv_bfloat16* __restrict__ Wlo,
        const float* __restrict__ bias,
        float* __restrict__ C, int M) {
    extern __shared__ __align__(16) __nv_bfloat16 smem[];
    uint32_t smb = (uint32_t)__cvta_generic_to_shared(smem);

    int tid  = threadIdx.x;
    int lane = tid & 31;
    int warp = tid >> 5;
    int wm = warp & 1;        // M offset 0/64
    int wn = warp >> 1;       // N offset 0/32/64/96

    int rowBase = blockIdx.y * GBM;
    int colBase = blockIdx.x * GBN;

    float acc[4][4][4];
#pragma unroll
    for (int mi = 0; mi < 4; mi++)
#pragma unroll
        for (int ni = 0; ni < 4; ni++)
#pragma unroll
            for (int r = 0; r < 4; r++) acc[mi][ni][r] = 0.0f;

    int ldrow = tid >> 1;            // 0..127
    int ldk   = (tid & 1) * 16;      // 0 or 16 (16 bf16 = 32B per array)
    bool aValid = (rowBase + ldrow) < M;
    const __nv_bfloat16* aHiSrc = Ahi + (long)(rowBase + ldrow) * K + ldk;
    const __nv_bfloat16* aLoSrc = Alo + (long)(rowBase + ldrow) * K + ldk;
    const __nv_bfloat16* bHiSrc = Whi + (long)(colBase + ldrow) * K + ldk;
    const __nv_bfloat16* bLoSrc = Wlo + (long)(colBase + ldrow) * K + ldk;
    uint32_t dstOff = (uint32_t)(ldrow * TS + ldk) * 2;

    int nT = K / GBK;

    // prologue: stage 0
    {
        uint32_t base = smb;
        cp16(base + OFF_AHI + dstOff,      aHiSrc,     aValid);
        cp16(base + OFF_AHI + dstOff + 16, aHiSrc + 8, aValid);
        cp16(base + OFF_ALO + dstOff,      aLoSrc,     aValid);
        cp16(base + OFF_ALO + dstOff + 16, aLoSrc + 8, aValid);
        cp16(base + OFF_BHI + dstOff,      bHiSrc,     true);
        cp16(base + OFF_BHI + dstOff + 16, bHiSrc + 8, true);
        cp16(base + OFF_BLO + dstOff,      bLoSrc,     true);
        cp16(base + OFF_BLO + dstOff + 16, bLoSrc + 8, true);
        asm volatile("cp.async.commit_group;" ::: "memory");
    }

    for (int ch = 0; ch < nT; ch++) {
        if (ch + 1 < nT) {
            int kt = (ch + 1) * GBK;
            uint32_t base = smb + ((ch + 1) & 1) * STAGE_BYTES;
            cp16(base + OFF_AHI + dstOff,      aHiSrc + kt,     aValid);
            cp16(base + OFF_AHI + dstOff + 16, aHiSrc + kt + 8, aValid);
            cp16(base + OFF_ALO + dstOff,      aLoSrc + kt,     aValid);
            cp16(base + OFF_ALO + dstOff + 16, aLoSrc + kt + 8, aValid);
            cp16(base + OFF_BHI + dstOff,      bHiSrc + kt,     true);
            cp16(base + OFF_BHI + dstOff + 16, bHiSrc + kt + 8, true);
            cp16(base + OFF_BLO + dstOff,      bLoSrc + kt,     true);
            cp16(base + OFF_BLO + dstOff + 16, bLoSrc + kt + 8, true);
            asm volatile("cp.async.commit_group;" ::: "memory");
            asm volatile("cp.async.wait_group 1;" ::: "memory");
        } else {
            asm volatile("cp.async.wait_group 0;" ::: "memory");
        }
        __syncthreads();

        uint32_t st = smb + (ch & 1) * STAGE_BYTES;
#pragma unroll
        for (int kk = 0; kk < GBK; kk += 16) {
            uint32_t ah[4][4], al[4][4], bh[4][2], bl[4][2];
            // A fragments: row = r0 + (lane&15), k = kk + (lane>>4)*8
            uint32_t aoff = (uint32_t)(((wm * 64) + (lane & 15)) * TS + kk + ((lane >> 4) << 3)) * 2;
#pragma unroll
            for (int mi = 0; mi < 4; mi++) {
                uint32_t ro = aoff + (uint32_t)(mi * 16 * TS) * 2;
                ldsm4(ah[mi], st + OFF_AHI + ro);
                ldsm4(al[mi], st + OFF_ALO + ro);
            }
            // B fragments: row n = n0 + (lane&7), k = kk + ((lane>>3)&1)*8
            uint32_t boff = (uint32_t)(((wn * 32) + (lane & 7)) * TS + kk + (((lane >> 3) & 1) << 3)) * 2;
#pragma unroll
            for (int ni = 0; ni < 4; ni++) {
                uint32_t ro = boff + (uint32_t)(ni * 8 * TS) * 2;
                ldsm2(bh[ni], st + OFF_BHI + ro);
                ldsm2(bl[ni], st + OFF_BLO + ro);
            }
#define MMA_B(AF, BF)                                                          \
            asm volatile(                                                      \
                "mma.sync.aligned.m16n8k16.row.col.f32.bf16.bf16.f32 "         \
                "{%0,%1,%2,%3}, {%4,%5,%6,%7}, {%8,%9}, {%0,%1,%2,%3};"        \
                : "+f"(acc[mi][ni][0]), "+f"(acc[mi][ni][1]),                  \
                  "+f"(acc[mi][ni][2]), "+f"(acc[mi][ni][3])                   \
                : "r"(AF[mi][0]), "r"(AF[mi][1]),                              \
                  "r"(AF[mi][2]), "r"(AF[mi][3]),                              \
                  "r"(BF[ni][0]), "r"(BF[ni][1]))
#pragma unroll
            for (int mi = 0; mi < 4; mi++)
#pragma unroll
                for (int ni = 0; ni < 4; ni++) { MMA_B(al, bh); }
#pragma unroll
            for (int mi = 0; mi < 4; mi++)
#pragma unroll
                for (int ni = 0; ni < 4; ni++) { MMA_B(ah, bl); }
#pragma unroll
            for (int mi = 0; mi < 4; mi++)
#pragma unroll
                for (int ni = 0; ni < 4; ni++) { MMA_B(ah, bh); }
#undef MMA_B
        }
        __syncthreads();
    }

    // epilogue: bias + relu + store (m16n8 accum layout)
#pragma unroll
    for (int mi = 0; mi < 4; mi++) {
        int r0 = rowBase + wm * 64 + mi * 16 + (lane >> 2);
#pragma unroll
        for (int ni = 0; ni < 4; ni++) {
            int col = colBase + wn * 32 + ni * 8 + (lane & 3) * 2;
            float b0 = bias[col], b1v = bias[col + 1];
            if (r0 < M) {
                float2 o;
                o.x = fmaxf(acc[mi][ni][0] + b0, 0.f);
                o.y = fmaxf(acc[mi][ni][1] + b1v, 0.f);
                *(float2*)&C[(long)r0 * HIDDEN + col] = o;
            }
            if (r0 + 8 < M) {
                float2 o;
                o.x = fmaxf(acc[mi][ni][2] + b0, 0.f);
                o.y = fmaxf(acc[mi][ni][3] + b1v, 0.f);
                *(float2*)&C[(long)(r0 + 8) * HIDDEN + col] = o;
            }
        }
    }
}

// ---------------- SpMM: fp32 gather-accumulate -> bf16 hi/lo output ----------------
__device__ __forceinline__ void store_hilo(__nv_bfloat16* hi, __nv_bfloat16* lo,
                                           long off, float4 acc) {
    __nv_bfloat16 hx = __float2bfloat16_rn(acc.x);
    __nv_bfloat16 hy = __float2bfloat16_rn(acc.y);
    __nv_bfloat16 hz = __float2bfloat16_rn(acc.z);
    __nv_bfloat16 hw = __float2bfloat16_rn(acc.w);
    __nv_bfloat162 h01; h01.x = hx; h01.y = hy;
    __nv_bfloat162 h23; h23.x = hz; h23.y = hw;
    __nv_bfloat162 l01, l23;
    l01.x = __float2bfloat16_rn(acc.x - __bfloat162float(hx));
    l01.y = __float2bfloat16_rn(acc.y - __bfloat162float(hy));
    l23.x = __float2bfloat16_rn(acc.z - __bfloat162float(hz));
    l23.y = __float2bfloat16_rn(acc.w - __bfloat162float(hw));
    *(__nv_bfloat162*)&hi[off]     = h01;
    *(__nv_bfloat162*)&hi[off + 2] = h23;
    *(__nv_bfloat162*)&lo[off]     = l01;
    *(__nv_bfloat162*)&lo[off + 2] = l23;
}

// 128-col: 1 warp per node (input fp32 x)
__global__ __launch_bounds__(256) void k_spmm128(const float* __restrict__ in,
                                                 __nv_bfloat16* __restrict__ outHi,
                                                 __nv_bfloat16* __restrict__ outLo) {
    int node = blockIdx.x * 8 + (threadIdx.x >> 5);
    if (node >= N_NODES) return;
    int c = (threadIdx.x & 31) * 4;
    int beg = node * BUCKET;
    int end = beg + g_fill[node];

    float4 acc = make_float4(0.f, 0.f, 0.f, 0.f);
    int e = beg;
    for (; e + 4 <= end; e += 4) {
        int4 p = *(const int4*)&g_csr[e];
        int4 q = *(const int4*)&g_csr[e + 2];
        float w0 = __int_as_float(p.y), w1 = __int_as_float(p.w);
        float w2 = __int_as_float(q.y), w3 = __int_as_float(q.w);
        float4 v0 = *(const float4*)&in[(long)p.x * F_IN + c];
        float4 v1 = *(const float4*)&in[(long)p.z * F_IN + c];
        float4 v2 = *(const float4*)&in[(long)q.x * F_IN + c];
        float4 v3 = *(const float4*)&in[(long)q.z * F_IN + c];
        acc.x = fmaf(v0.x, w0, acc.x); acc.y = fmaf(v0.y, w0, acc.y);
        acc.z = fmaf(v0.z, w0, acc.z); acc.w = fmaf(v0.w, w0, acc.w);
        acc.x = fmaf(v1.x, w1, acc.x); acc.y = fmaf(v1.y, w1, acc.y);
        acc.z = fmaf(v1.z, w1, acc.z); acc.w = fmaf(v1.w, w1, acc.w);
        acc.x = fmaf(v2.x, w2, acc.x); acc.y = fmaf(v2.y, w2, acc.y);
        acc.z = fmaf(v2.z, w2, acc.z); acc.w = fmaf(v2.w, w2, acc.w);
        acc.x = fmaf(v3.x, w3, acc.x); acc.y = fmaf(v3.y, w3, acc.y);
        acc.z = fmaf(v3.z, w3, acc.z); acc.w = fmaf(v3.w, w3, acc.w);
    }
    for (; e < end; e++) {
        int2 p = g_csr[e];
        float w = __int_as_float(p.y);
        float4 v = *(const float4*)&in[(long)p.x * F_IN + c];
        acc.x = fmaf(v.x, w, acc.x); acc.y = fmaf(v.y, w, acc.y);
        acc.z = fmaf(v.z, w, acc.z); acc.w = fmaf(v.w, w, acc.w);
    }
    store_hilo(outHi, outLo, (long)node * F_IN + c, acc);
}

// 256-col: 64 threads per node (input fp32 h1)
__global__ __launch_bounds__(256) void k_spmm256(const float* __restrict__ in,
                                                 __nv_bfloat16* __restrict__ outHi,
                                                 __nv_bfloat16* __restrict__ outLo) {
    int node = blockIdx.x * 4 + (threadIdx.x >> 6);
    if (node >= N_NODES) return;
    int c = (threadIdx.x & 63) * 4;
    int beg = node * BUCKET;
    int end = beg + g_fill[node];

    float4 acc = make_float4(0.f, 0.f, 0.f, 0.f);
    int e = beg;
    for (; e + 4 <= end; e += 4) {
        int4 p = *(const int4*)&g_csr[e];
        int4 q = *(const int4*)&g_csr[e + 2];
        float w0 = __int_as_float(p.y), w1 = __int_as_float(p.w);
        float w2 = __int_as_float(q.y), w3 = __int_as_float(q.w);
        float4 v0 = *(const float4*)&in[(long)p.x * HIDDEN + c];
        float4 v1 = *(const float4*)&in[(long)p.z * HIDDEN + c];
        float4 v2 = *(const float4*)&in[(long)q.x * HIDDEN + c];
        float4 v3 = *(const float4*)&in[(long)q.z * HIDDEN + c];
        acc.x = fmaf(v0.x, w0, acc.x); acc.y = fmaf(v0.y, w0, acc.y);
        acc.z = fmaf(v0.z, w0, acc.z); acc.w = fmaf(v0.w, w0, acc.w);
        acc.x = fmaf(v1.x, w1, acc.x); acc.y = fmaf(v1.y, w1, acc.y);
        acc.z = fmaf(v1.z, w1, acc.z); acc.w = fmaf(v1.w, w1, acc.w);
        acc.x = fmaf(v2.x, w2, acc.x); acc.y = fmaf(v2.y, w2, acc.y);
        acc.z = fmaf(v2.z, w2, acc.z); acc.w = fmaf(v2.w, w2, acc.w);
        acc.x = fmaf(v3.x, w3, acc.x); acc.y = fmaf(v3.y, w3, acc.y);
        acc.z = fmaf(v3.z, w3, acc.z); acc.w = fmaf(v3.w, w3, acc.w);
    }
    for (; e < end; e++) {
        int2 p = g_csr[e];
        float w = __int_as_float(p.y);
        float4 v = *(const float4*)&in[(long)p.x * HIDDEN + c];
        acc.x = fmaf(v.x, w, acc.x); acc.y = fmaf(v.y, w, acc.y);
        acc.z = fmaf(v.z, w, acc.z); acc.w = fmaf(v.w, w, acc.w);
    }
    store_hilo(outHi, outLo, (long)node * HIDDEN + c, acc);
}

// ---------------- fused pool + head ----------------
__global__ __launch_bounds__(256) void k_poolhead(const float* __restrict__ h,
                                                  const float* __restrict__ Wd,
                                                  const float* __restrict__ bd,
                                                  const float* __restrict__ Wo,
                                                  const float* __restrict__ bo,
                                                  float* __restrict__ out) {
    __shared__ float pg[HIDDEN];
    __shared__ float red[256];
    int g = blockIdx.x;
    int j = threadIdx.x;
    int beg = g_gstart[g], end = g_gstart[g + 1];

    float acc0 = 0.f, acc1 = 0.f, acc2 = 0.f, acc3 = 0.f;
    int n = beg;
    for (; n + 4 <= end; n += 4) {
        acc0 += h[(long)n * HIDDEN + j];
        acc1 += h[(long)(n + 1) * HIDDEN + j];
        acc2 += h[(long)(n + 2) * HIDDEN + j];
        acc3 += h[(long)(n + 3) * HIDDEN + j];
    }
    for (; n < end; n++) acc0 += h[(long)n * HIDDEN + j];
    pg[j] = (acc0 + acc1) + (acc2 + acc3);
    __syncthreads();

    float acc = 0.f;
#pragma unroll 8
    for (int k = 0; k < HIDDEN; k++)
        acc = fmaf(pg[k], Wd[k * HIDDEN + j], acc);
    float v = fmaxf(acc + bd[j], 0.f);
    red[j] = v * Wo[j];
    __syncthreads();
    for (int s = 128; s > 0; s >>= 1) {
        if (j < s) red[j] += red[j + s];
        __syncthreads();
    }
    if (j == 0) out[g] = red[0] + bo[0];
}

// ---------------- launch ----------------
extern "C" void kernel_launch(void* const* d_in, const int* in_sizes, int n_in,
                              void* d_out, int out_size) {
    const float* x        = (const float*)d_in[0];
    const int*   edge_src = (const int*)d_in[1];
    const int*   edge_dst = (const int*)d_in[2];
    const float* edge_w   = (const float*)d_in[3];
    const int*   seg_ids  = (const int*)d_in[4];
    const float* W1       = (const float*)d_in[5];
    const float* b1       = (const float*)d_in[6];
    const float* W2       = (const float*)d_in[7];
    const float* b2       = (const float*)d_in[8];
    const float* Wd       = (const float*)d_in[9];
    const float* bd       = (const float*)d_in[10];
    const float* Wo       = (const float*)d_in[11];
    const float* bo       = (const float*)d_in[12];
    float* out = (float*)d_out;

    float* bufA; cudaGetSymbolAddress((void**)&bufA, g_bufA);
    float* bufB; cudaGetSymbolAddress((void**)&bufB, g_bufB);
    __nv_bfloat16* sHi; cudaGetSymbolAddress((void**)&sHi, g_sHi);
    __nv_bfloat16* sLo; cudaGetSymbolAddress((void**)&sLo, g_sLo);
    __nv_bfloat16* w1hi; cudaGetSymbolAddress((void**)&w1hi, g_W1hi);
    __nv_bfloat16* w1lo; cudaGetSymbolAddress((void**)&w1lo, g_W1lo);
    __nv_bfloat16* w2hi; cudaGetSymbolAddress((void**)&w2hi, g_W2hi);
    __nv_bfloat16* w2lo; cudaGetSymbolAddress((void**)&w2lo, g_W2lo);

    cudaFuncSetAttribute(k_gemm_pipe, cudaFuncAttributeMaxDynamicSharedMemorySize, GEMM_SMEM);

    // setup + scatter
    k_setup<<<(HIDDEN * HIDDEN + 255) / 256, 256>>>(seg_ids, W1, W2);
    k_scatter<<<(N_EDGES + 255) / 256, 256>>>(edge_src, edge_dst, edge_w);

    dim3 gemmGrid(HIDDEN / GBN, (N_NODES + GBM - 1) / GBM);

    // layer 1: s1 = A@x (bf16 hi/lo); h1 = relu(s1 @ W1 + b1)
    k_spmm128<<<(N_NODES + 7) / 8, 256>>>(x, sHi, sLo);
    k_gemm_pipe<<<gemmGrid, 256, GEMM_SMEM>>>(sHi, sLo, F_IN, w1hi, w1lo, b1, bufA, N_NODES);

    // layer 2: s2 = A@h1 (bf16 hi/lo); h2 = relu(s2 @ W2 + b2)
    k_spmm256<<<(N_NODES + 3) / 4, 256>>>(bufA, sHi, sLo);
    k_gemm_pipe<<<gemmGrid, 256, GEMM_SMEM>>>(sHi, sLo, HIDDEN, w2hi, w2lo, b2, bufB, N_NODES);

    // fused pool + head
    k_poolhead<<<N_GRAPHS, HIDDEN>>>(bufB, Wd, bd, Wo, bo, out);
}